// round 12
// baseline (speedup 1.0000x reference)
#include <cuda_runtime.h>
#include <cuda_bf16.h>
#include <cstdint>

// Per-pixel dynamic 5x5 conv, channel-shared taps.
// x: [B=8, C=64, H=256, W=256] f32; w: [25, B, 1, H, W] f32
//
// Warp-private 4-stage cp.async.cg pipelines (16B staging, no __syncthreads),
// 2x2 quad/thread, parity-split FFMA2/FFMA math. This round: register diet to
// fit 4 CTAs/SM (<=128 regs): rolling row window removed, dead unpacks gone,
// minimal infrastructure. Occupancy 12 -> 16 warps/SM.

#define BB 8
#define HW 65536
#define HH_DIM 256
#define WW_DIM 256
#define TH 16
#define TW 32
#define SMW 40                // row stride (floats) == 10 float4, fully staged
#define WROWS 8               // rows per warp slab (4 out + 4 halo)
#define WSTAGE (WROWS * SMW)  // 320 floats per stage
#define NSLOT4 80
#define CPERCTA 32
#define NSTAGE 4
#define PFD 3

__device__ __forceinline__ void cp_async16(uint32_t saddr, const void* gaddr, int src_size) {
    asm volatile("cp.async.cg.shared.global [%0], [%1], 16, %2;"
                 :: "r"(saddr), "l"(gaddr), "r"(src_size));
}
__device__ __forceinline__ void cp_commit() {
    asm volatile("cp.async.commit_group;");
}
template <int N>
__device__ __forceinline__ void cp_wait() {
    asm volatile("cp.async.wait_group %0;" :: "n"(N));
}

__device__ __forceinline__ uint64_t lds64(uint32_t a) {
    uint64_t v; asm volatile("ld.shared.b64 %0, [%1];" : "=l"(v) : "r"(a)); return v;
}
__device__ __forceinline__ void ffma2(uint64_t& d, uint64_t a, uint64_t b) {
    asm("fma.rn.f32x2 %0, %1, %2, %0;" : "+l"(d) : "l"(a), "l"(b));
}
__device__ __forceinline__ uint64_t addf32x2(uint64_t a, uint64_t b) {
    uint64_t r; asm("add.rn.f32x2 %0, %1, %2;" : "=l"(r) : "l"(a), "l"(b)); return r;
}
__device__ __forceinline__ void unpack2f(uint64_t v, float& lo, float& hi) {
    asm("mov.b64 {%0, %1}, %2;" : "=f"(lo), "=f"(hi) : "l"(v));
}
// extract only one half (lets ptxas alias without materializing the other)
__device__ __forceinline__ float lo_f(uint64_t v) {
    float a, b; unpack2f(v, a, b); return a;
}
__device__ __forceinline__ float hi_f(uint64_t v) {
    float a, b; unpack2f(v, a, b); return b;
}

__global__ __launch_bounds__(128, 4)
void dynconv5x5_kernel(const float* __restrict__ x,
                       const float* __restrict__ wgt,
                       float* __restrict__ out) {
    __shared__ float sm[4][NSTAGE][WSTAGE];   // [warp][stage][slab]

    const int tid  = threadIdx.x;
    const int wid  = tid >> 5;
    const int lane = tid & 31;
    const int qx   = lane & 15;
    const int qy   = lane >> 4;
    const int w0   = blockIdx.x * TW;
    const int h0   = blockIdx.y * TH;
    const int z    = blockIdx.z;
    const int b    = z >> 1;
    const int c0   = (z & 1) * CPERCTA;

    const int slab0 = h0 + wid * 4;
    const int oh    = slab0 + qy * 2;
    const int ow    = w0 + qx * 2;

    // ---- weights, split by tap x-offset parity (100 regs total)
    uint64_t wtp[15], wbp[15];                      // even-ww packed pairs
    float wtsl[10], wtsh[10], wbsl[10], wbsh[10];   // odd-ww scalar halves
#pragma unroll
    for (int r = 0; r < 5; r++) {
#pragma unroll
        for (int ww = 0; ww < 5; ww++) {
            const float* wp = &wgt[(((size_t)(r * 5 + ww) * BB + b) * HH_DIM + oh) * WW_DIM + ow];
            uint64_t t  = *(const uint64_t*)(wp);
            uint64_t bo = *(const uint64_t*)(wp + WW_DIM);
            if ((ww & 1) == 0) {
                wtp[r * 3 + ww / 2] = t;
                wbp[r * 3 + ww / 2] = bo;
            } else {
                int j = r * 2 + (ww == 3);
                unpack2f(t,  wtsl[j], wtsh[j]);
                unpack2f(bo, wbsl[j], wbsh[j]);
            }
        }
    }

    // ---- 16B staging slots (80 float4 = 8 rows x 10; col c <-> gw w0-4+c)
    int xoff[3];
    int ssz [3];
    int soff[3];
    const int nslot_here = (lane < 16) ? 3 : 2;
#pragma unroll
    for (int j = 0; j < 3; j++) {
        int i    = lane + j * 32;
        int r    = i / 10;
        int col4 = i - r * 10;
        int gh = slab0 + r - 2;
        int gw = w0 - 4 + col4 * 4;
        bool v = (i < NSLOT4) && gh >= 0 && gh < HH_DIM && gw >= 0 && gw < WW_DIM;
        xoff[j] = gh * WW_DIM + gw;
        ssz[j]  = v ? 16 : 0;
        soff[j] = (r * SMW + col4 * 4) * 4;
    }

    const float* xc = x   + ((size_t)b * 64 + c0) * HW;
    float*       ob = out + (((size_t)b * 64 + c0) * HW) + oh * WW_DIM + ow;

    const uint32_t wbase = (uint32_t)__cvta_generic_to_shared(&sm[wid][0][0]);
    const uint32_t cbase = wbase + ((qy * 2) * SMW + (qx * 2 + 2)) * 4;

    // ---- prologue: stage channels 0..PFD-1
#pragma unroll
    for (int p = 0; p < PFD; p++) {
        const float* xp = xc + (size_t)p * HW;
        const uint32_t sp = wbase + p * (WSTAGE * 4);
        cp_async16(sp + soff[0], xp + xoff[0], ssz[0]);
        cp_async16(sp + soff[1], xp + xoff[1], ssz[1]);
        if (nslot_here == 3) cp_async16(sp + soff[2], xp + xoff[2], ssz[2]);
        cp_commit();
    }

#pragma unroll 4
    for (int c = 0; c < CPERCTA; c++) {
        if (c + PFD < CPERCTA) cp_wait<PFD - 1>(); else cp_wait<0>();
        __syncwarp(0xffffffffu);

        const uint32_t sbase = cbase + (c & (NSTAGE - 1)) * (WSTAGE * 4);

        uint64_t atp = 0, atq = 0, abp = 0, abq = 0;
        float ats0 = 0.f, ats1 = 0.f, abs0 = 0.f, abs1 = 0.f;
#pragma unroll
        for (int r = 0; r < 6; r++) {
            uint32_t base = sbase + r * (SMW * 4);
            uint64_t p0 = lds64(base);        // {x0,x1}
            uint64_t p2 = lds64(base + 8);    // {x2,x3}
            uint64_t p4 = lds64(base + 16);   // {x4,x5}
            float x1 = hi_f(p0);
            float x2 = lo_f(p2);
            float x3 = hi_f(p2);
            float x4 = lo_f(p4);
            if (r < 5) {
                ffma2(atp, p0, wtp[r * 3 + 0]);
                ffma2(atq, p2, wtp[r * 3 + 1]);
                ffma2(atp, p4, wtp[r * 3 + 2]);
                ats0 = fmaf(x1, wtsl[r * 2 + 0], ats0);
                ats1 = fmaf(x2, wtsh[r * 2 + 0], ats1);
                ats0 = fmaf(x3, wtsl[r * 2 + 1], ats0);
                ats1 = fmaf(x4, wtsh[r * 2 + 1], ats1);
            }
            if (r >= 1) {
                int q = r - 1;
                ffma2(abp, p0, wbp[q * 3 + 0]);
                ffma2(abq, p2, wbp[q * 3 + 1]);
                ffma2(abp, p4, wbp[q * 3 + 2]);
                abs0 = fmaf(x1, wbsl[q * 2 + 0], abs0);
                abs1 = fmaf(x2, wbsh[q * 2 + 0], abs1);
                abs0 = fmaf(x3, wbsl[q * 2 + 1], abs0);
                abs1 = fmaf(x4, wbsh[q * 2 + 1], abs1);
            }
        }

        float tl, th, bl, bh;
        unpack2f(addf32x2(atp, atq), tl, th);
        unpack2f(addf32x2(abp, abq), bl, bh);

        float* o = ob + (size_t)c * HW;
        *(float2*)(o)          = make_float2(tl + ats0, th + ats1);
        *(float2*)(o + WW_DIM) = make_float2(bl + abs0, bh + abs1);

        if (c + PFD < CPERCTA) {
            const float* xn = xc + (size_t)(c + PFD) * HW;
            const uint32_t sn = wbase + ((c + PFD) & (NSTAGE - 1)) * (WSTAGE * 4);
            cp_async16(sn + soff[0], xn + xoff[0], ssz[0]);
            cp_async16(sn + soff[1], xn + xoff[1], ssz[1]);
            if (nslot_here == 3) cp_async16(sn + soff[2], xn + xoff[2], ssz[2]);
            cp_commit();
        }
    }
}

extern "C" void kernel_launch(void* const* d_in, const int* in_sizes, int n_in,
                              void* d_out, int out_size) {
    const float* x   = (const float*)d_in[0];
    const float* wgt = (const float*)d_in[1];
    float*       out = (float*)d_out;

    dim3 grid(WW_DIM / TW, HH_DIM / TH, BB * 2);   // 2048 blocks
    dim3 block(128);
    dynconv5x5_kernel<<<grid, block>>>(x, wgt, out);
}